// round 1
// baseline (speedup 1.0000x reference)
#include <cuda_runtime.h>
#include <cuda_bf16.h>
#include <cstddef>

// Problem constants
#define BB 16
#define CC 256
#define HH 64
#define WW 64
#define NHEAD 8
#define HD 32
#define NPIX 4096   // H*W

// Scratch (device globals; no allocations allowed)
__device__ float g_x[(size_t)BB * CC * NPIX];          // 16.8M floats
__device__ float g_qkv[(size_t)BB * 3 * CC * NPIX];    // 50.3M floats
__device__ float g_stats[BB * NHEAD * HD * 2];         // (max, sum) per row
__device__ float g_lambda[BB * NHEAD * HD * HD];       // (b', i, o)
__device__ float g_result[(size_t)BB * CC * NPIX];

// ---------------------------------------------------------------------------
// K1: 3x3 conv (C->C), + bias + residual.  grid (4, 64, 16) = (oc/64, h, b)
// block 256 = (tx 16 w-groups) x (ty 16 o-groups); each thread 4o x 4w
// ---------------------------------------------------------------------------
__global__ __launch_bounds__(256) void conv3_kernel(
    const float* __restrict__ src, const float* __restrict__ wgt,
    const float* __restrict__ bias, float* __restrict__ out)
{
    const int oc0 = blockIdx.x * 64;
    const int h   = blockIdx.y;
    const int b   = blockIdx.z;
    const int tid = threadIdx.x;
    const int tx = tid & 15, ty = tid >> 4;

    __shared__ float in_s[8][3][66];   // 8 c x 3 rows x 66 cols (w -1..64)
    __shared__ float w_s[8][9][65];    // 8 c x 9 taps x 64 o (padded)

    float acc[4][4] = {};
    const float* srcb = src + (size_t)b * CC * NPIX;

    for (int cc = 0; cc < CC; cc += 8) {
        // load input slab
        for (int idx = tid; idx < 8 * 3 * 66; idx += 256) {
            int c   = idx / (3 * 66);
            int rem = idx % (3 * 66);
            int r   = rem / 66;
            int col = rem % 66;
            int hh = h + r - 1;
            int wc = col - 1;
            float v = 0.f;
            if (hh >= 0 && hh < HH && wc >= 0 && wc < WW)
                v = srcb[(size_t)(cc + c) * NPIX + hh * WW + wc];
            in_s[c][r][col] = v;
        }
        // load weight slab: idx = o*72 + c*9 + t
        for (int idx = tid; idx < 8 * 9 * 64; idx += 256) {
            int o   = idx / 72;
            int rem = idx % 72;
            int c   = rem / 9;
            int t   = rem % 9;
            w_s[c][t][o] = wgt[(size_t)(oc0 + o) * (CC * 9) + (cc + c) * 9 + t];
        }
        __syncthreads();

        #pragma unroll
        for (int c = 0; c < 8; c++) {
            #pragma unroll
            for (int kh = 0; kh < 3; kh++) {
                float iv[6];
                #pragma unroll
                for (int m = 0; m < 6; m++) iv[m] = in_s[c][kh][tx * 4 + m];
                #pragma unroll
                for (int kw = 0; kw < 3; kw++) {
                    float wv[4];
                    #pragma unroll
                    for (int jo = 0; jo < 4; jo++) wv[jo] = w_s[c][kh * 3 + kw][ty * 4 + jo];
                    #pragma unroll
                    for (int jo = 0; jo < 4; jo++)
                        #pragma unroll
                        for (int jw = 0; jw < 4; jw++)
                            acc[jo][jw] += wv[jo] * iv[jw + kw];
                }
            }
        }
        __syncthreads();
    }

    #pragma unroll
    for (int jo = 0; jo < 4; jo++) {
        int o = oc0 + ty * 4 + jo;
        float bsv = bias[o];
        #pragma unroll
        for (int jw = 0; jw < 4; jw++) {
            int w = tx * 4 + jw;
            size_t off = ((size_t)b * CC + o) * NPIX + h * WW + w;
            out[off] = acc[jo][jw] + bsv + src[off];
        }
    }
}

// ---------------------------------------------------------------------------
// K2/K6: 1x1 conv as GEMM: out[b,o,n] = sum_k W[o,k]*in[b,k,n] (+ bias)
// grid (N/64, O/64, B); block 256; each thread 4o x 4n
// ---------------------------------------------------------------------------
__global__ __launch_bounds__(256) void gemm_nchw(
    const float* __restrict__ Wm, const float* __restrict__ bias,
    const float* __restrict__ in, float* __restrict__ out,
    int O, int K, int NTOT)
{
    const int n0 = blockIdx.x * 64;
    const int o0 = blockIdx.y * 64;
    const int b  = blockIdx.z;
    const int tid = threadIdx.x;
    const int tx = tid & 15, ty = tid >> 4;

    __shared__ float As[16][65];   // [k][o]
    __shared__ float Bs[16][65];   // [k][n]

    const float* inb = in + (size_t)b * K * NTOT;
    float acc[4][4] = {};

    for (int k0 = 0; k0 < K; k0 += 16) {
        for (int idx = tid; idx < 1024; idx += 256) {
            int o = idx >> 4, k = idx & 15;
            As[k][o] = Wm[(size_t)(o0 + o) * K + k0 + k];
        }
        for (int idx = tid; idx < 1024; idx += 256) {
            int k = idx >> 6, n = idx & 63;
            Bs[k][n] = inb[(size_t)(k0 + k) * NTOT + n0 + n];
        }
        __syncthreads();
        #pragma unroll
        for (int k = 0; k < 16; k++) {
            float a[4], bv[4];
            #pragma unroll
            for (int jo = 0; jo < 4; jo++) a[jo] = As[k][ty * 4 + jo];
            #pragma unroll
            for (int jn = 0; jn < 4; jn++) bv[jn] = Bs[k][tx * 4 + jn];
            #pragma unroll
            for (int jo = 0; jo < 4; jo++)
                #pragma unroll
                for (int jn = 0; jn < 4; jn++) acc[jo][jn] += a[jo] * bv[jn];
        }
        __syncthreads();
    }

    #pragma unroll
    for (int jo = 0; jo < 4; jo++) {
        int o = o0 + ty * 4 + jo;
        float bs = bias ? bias[o] : 0.f;
        #pragma unroll
        for (int jn = 0; jn < 4; jn++)
            out[((size_t)b * O + o) * NTOT + n0 + tx * 4 + jn] = acc[jo][jn] + bs;
    }
}

// ---------------------------------------------------------------------------
// K3: per-row (b', i) max and sum(exp) over n=4096.  grid 4096, block 256
// ---------------------------------------------------------------------------
__global__ __launch_bounds__(256) void softmax_stats_kernel(float* __restrict__ stats)
{
    const int row  = blockIdx.x;          // b'*32 + i
    const int bp   = row >> 5, i = row & 31;
    const int b    = bp >> 3, head = bp & 7;
    const float* kptr = g_qkv + ((size_t)b * 3 * CC + CC + head * HD + i) * NPIX;

    __shared__ float red[256];
    const int t = threadIdx.x;

    float m = -1e30f;
    for (int n = t; n < NPIX; n += 256) m = fmaxf(m, kptr[n]);
    red[t] = m; __syncthreads();
    for (int s = 128; s > 0; s >>= 1) {
        if (t < s) red[t] = fmaxf(red[t], red[t + s]);
        __syncthreads();
    }
    m = red[0];
    __syncthreads();

    float sum = 0.f;
    for (int n = t; n < NPIX; n += 256) sum += __expf(kptr[n] - m);
    red[t] = sum; __syncthreads();
    for (int s = 128; s > 0; s >>= 1) {
        if (t < s) red[t] += red[t + s];
        __syncthreads();
    }
    if (t == 0) { stats[row * 2] = m; stats[row * 2 + 1] = red[0]; }
}

// ---------------------------------------------------------------------------
// K4: content_lambda[b',i,o] = sum_n softmax(k)[i,n] * v[o,n].  grid 128.
// ---------------------------------------------------------------------------
__global__ __launch_bounds__(256) void lambda_kernel(const float* __restrict__ stats,
                                                     float* __restrict__ lam)
{
    const int bp = blockIdx.x;
    const int b = bp >> 3, head = bp & 7;
    const float* kbase = g_qkv + ((size_t)b * 3 * CC + CC + head * HD) * NPIX;
    const float* vbase = g_qkv + ((size_t)b * 3 * CC + 2 * CC + head * HD) * NPIX;

    __shared__ float kf[32][129];
    __shared__ float vv[32][129];
    __shared__ float mi[32], si[32];

    const int tid = threadIdx.x;
    if (tid < 32) {
        mi[tid] = stats[(bp * 32 + tid) * 2];
        si[tid] = 1.f / stats[(bp * 32 + tid) * 2 + 1];
    }
    __syncthreads();

    const int o  = tid & 31;
    const int ib = (tid >> 5) * 4;
    float acc[4] = {};

    for (int n0 = 0; n0 < NPIX; n0 += 128) {
        for (int idx = tid; idx < 32 * 128; idx += 256) {
            int r = idx >> 7, n = idx & 127;
            kf[r][n] = __expf(kbase[(size_t)r * NPIX + n0 + n] - mi[r]) * si[r];
            vv[r][n] = vbase[(size_t)r * NPIX + n0 + n];
        }
        __syncthreads();
        #pragma unroll 4
        for (int n = 0; n < 128; n++) {
            float vval = vv[o][n];
            #pragma unroll
            for (int j = 0; j < 4; j++) acc[j] += kf[ib + j][n] * vval;
        }
        __syncthreads();
    }
    #pragma unroll
    for (int j = 0; j < 4; j++) lam[(size_t)bp * 1024 + (ib + j) * 32 + o] = acc[j];
}

// ---------------------------------------------------------------------------
// K5: fused content + depthwise 5x5 pos-lambda + combine.
// grid (16 htiles, 2 o-halves, 128 b'); block 256; tile 4 rows x 64 w.
// Each thread = one pixel n, computes 16 output channels.
// ---------------------------------------------------------------------------
__global__ __launch_bounds__(256) void fused_kernel(const float* __restrict__ lam,
                                                    const float* __restrict__ rel,
                                                    float* __restrict__ res)
{
    const int h0 = blockIdx.x * 4;
    const int o0 = blockIdx.y * 16;
    const int bp = blockIdx.z;
    const int b = bp >> 3, head = bp & 7;

    const float* qbase = g_qkv + ((size_t)b * 3 * CC + head * HD) * NPIX;
    const float* vbase = g_qkv + ((size_t)b * 3 * CC + 2 * CC + head * HD) * NPIX;

    __shared__ float lam_s[32][17];     // [i][oo], pre-scaled
    __shared__ float rel_s[16][25];
    __shared__ float v_s[16][8][68];    // rows h0-2..h0+5, cols -2..65

    const int tid = threadIdx.x;
    const float scale = 0.1767766953f;  // hd^-0.5

    for (int idx = tid; idx < 32 * 16; idx += 256) {
        int i = idx >> 4, oo = idx & 15;
        lam_s[i][oo] = lam[(size_t)bp * 1024 + i * 32 + o0 + oo] * scale;
    }
    for (int idx = tid; idx < 16 * 25; idx += 256)
        rel_s[idx / 25][idx % 25] = rel[(o0 + idx / 25) * 25 + idx % 25];
    for (int idx = tid; idx < 16 * 8 * 68; idx += 256) {
        int o = idx / 544;
        int rem = idx % 544;
        int r = rem / 68, c = rem % 68;
        int h = h0 - 2 + r, w = c - 2;
        float val = 0.f;
        if (h >= 0 && h < HH && w >= 0 && w < WW)
            val = vbase[(size_t)(o0 + o) * NPIX + h * WW + w];
        v_s[o][r][c] = val;
    }
    __syncthreads();

    const int wr = tid >> 6;    // 0..3
    const int w  = tid & 63;
    const int n  = (h0 + wr) * WW + w;

    float qreg[32];
    #pragma unroll
    for (int i = 0; i < 32; i++) qreg[i] = qbase[(size_t)i * NPIX + n];

    float* outb = res + ((size_t)b * CC + head * HD + o0) * NPIX + n;

    #pragma unroll 2
    for (int oo = 0; oo < 16; oo++) {
        float content = 0.f;
        #pragma unroll
        for (int i = 0; i < 32; i++) content += qreg[i] * lam_s[i][oo];
        float pos = 0.f;
        #pragma unroll
        for (int dh = 0; dh < 5; dh++)
            #pragma unroll
            for (int dw = 0; dw < 5; dw++)
                pos += rel_s[oo][dh * 5 + dw] * v_s[oo][wr + dh][w + dw];
        outb[(size_t)oo * NPIX] = content + qreg[o0 + oo] * pos;
    }
}

// ---------------------------------------------------------------------------
extern "C" void kernel_launch(void* const* d_in, const int* in_sizes, int n_in,
                              void* d_out, int out_size)
{
    const float* src   = (const float*)d_in[0];
    const float* rel   = (const float*)d_in[1];
    const float* qkv_w = (const float*)d_in[2];
    const float* cpe_w = (const float*)d_in[3];
    const float* cpe_b = (const float*)d_in[4];
    const float* out_w = (const float*)d_in[5];
    const float* out_b = (const float*)d_in[6];
    float* out = (float*)d_out;

    float *px, *pqkv, *pstats, *plam, *pres;
    cudaGetSymbolAddress((void**)&px,    g_x);
    cudaGetSymbolAddress((void**)&pqkv,  g_qkv);
    cudaGetSymbolAddress((void**)&pstats,g_stats);
    cudaGetSymbolAddress((void**)&plam,  g_lambda);
    cudaGetSymbolAddress((void**)&pres,  g_result);

    // 1) CPE conv + residual -> x
    conv3_kernel<<<dim3(4, 64, 16), 256>>>(src, cpe_w, cpe_b, px);
    // 2) qkv = qkv_w @ x
    gemm_nchw<<<dim3(64, 12, 16), 256>>>(qkv_w, nullptr, px, pqkv, 3 * CC, CC, NPIX);
    // 3) softmax row stats over k
    softmax_stats_kernel<<<4096, 256>>>(pstats);
    // 4) content lambda
    lambda_kernel<<<128, 256>>>(pstats, plam);
    // 5) fused content + pos-lambda + combine
    fused_kernel<<<dim3(16, 2, 128), 256>>>(plam, rel, pres);
    // 6) output projection
    gemm_nchw<<<dim3(64, 4, 16), 256>>>(out_w, out_b, pres, out, CC, CC, NPIX);
}

// round 6
// speedup vs baseline: 3.3598x; 3.3598x over previous
#include <cuda_runtime.h>
#include <cuda_bf16.h>
#include <cstdint>
#include <cstddef>

#define BB 16
#define CC 256
#define HH 64
#define WW 64
#define NHEAD 8
#define HD 32
#define NPIX 4096

// Scratch (device globals; no allocations allowed)
__device__ float g_x[(size_t)BB * CC * NPIX];
__device__ float g_qkv[(size_t)BB * 3 * CC * NPIX];
__device__ float g_stats[BB * NHEAD * HD * 2];
__device__ float g_lambda[BB * NHEAD * HD * HD];
__device__ float g_lampart[BB * NHEAD * 8 * HD * HD];
__device__ float g_result[(size_t)BB * CC * NPIX];
__device__ float g_wt[CC * CC * 9];   // [o][tap*256+c]

// ---------------------------------------------------------------------------
// bf16 split helpers: x = hi + lo (both bf16), |x - hi - lo| ~ 2^-18 |x|
// ---------------------------------------------------------------------------
__device__ __forceinline__ void bf16_split(float x, __nv_bfloat16& hi, __nv_bfloat16& lo) {
    hi = __float2bfloat16_rn(x);
    lo = __float2bfloat16_rn(x - __bfloat162float(hi));
}

__device__ __forceinline__ void mma_bf16(float* d, const uint32_t* a, const uint32_t* b) {
    asm volatile(
        "mma.sync.aligned.m16n8k16.row.col.f32.bf16.bf16.f32 "
        "{%0,%1,%2,%3}, {%4,%5,%6,%7}, {%8,%9}, {%0,%1,%2,%3};"
        : "+f"(d[0]), "+f"(d[1]), "+f"(d[2]), "+f"(d[3])
        : "r"(a[0]), "r"(a[1]), "r"(a[2]), "r"(a[3]), "r"(b[0]), "r"(b[1]));
}

// ---------------------------------------------------------------------------
// Tensor-core GEMM / implicit conv via mma.sync (HMMA), bf16 3-term split.
// D[b, o0+o, n0+n] = sum_k A[o][k] * X-tile[k][n]  (+bias) (+resid)
// A: [O][Ktot] row-major fp32 weights. conv=1: X-tile[k=tap*256+c][n] =
// in[b][c][pix shifted by tap] (zero-pad). Tiles M=128, N=128, K-slab=32.
// 8 warps, each 32(M) x 64(N). SMEM stride 40 bf16 -> conflict-free LDS.
// ---------------------------------------------------------------------------
#define ASTRIDE 40

__global__ void __launch_bounds__(256, 2)
gemm_mma(const float* __restrict__ A, const float* __restrict__ X,
         float* __restrict__ out, const float* __restrict__ bias,
         const float* __restrict__ resid, int nslabs, int O, int Ktot, int conv)
{
    __shared__ __align__(16) __nv_bfloat16 sA[2][128 * ASTRIDE];  // [hi/lo][o][k]
    __shared__ __align__(16) __nv_bfloat16 sB[2][128 * ASTRIDE];  // [hi/lo][n][k]

    const int tid  = threadIdx.x;
    const int warp = tid >> 5, lane = tid & 31;
    const int mw = warp & 3, nw = warp >> 2;     // warp grid 4(M) x 2(N)
    const int g  = lane >> 2, t = lane & 3;
    const int n0 = blockIdx.x * 128;
    const int o0 = blockIdx.y * 128;
    const int b  = blockIdx.z;

    const float* Xb = X + (size_t)b * (conv ? 256 : Ktot) * NPIX;

    float acc[2][8][4];
    #pragma unroll
    for (int mt = 0; mt < 2; mt++)
        #pragma unroll
        for (int nt = 0; nt < 8; nt++)
            #pragma unroll
            for (int r = 0; r < 4; r++) acc[mt][nt][r] = 0.f;

    for (int s = 0; s < nslabs; s++) {
        // ---- fill A slab: 128 o x 32 k
        {
            const int k0 = s * 32;
            #pragma unroll
            for (int it = 0; it < 4; it++) {
                int idx = tid + it * 256;       // 1024 = 128 o x 8 kq
                int kq = idx & 7, o = idx >> 3;
                float4 v = *(const float4*)(A + (size_t)(o0 + o) * Ktot + k0 + kq * 4);
                __nv_bfloat16 h[4], l[4];
                bf16_split(v.x, h[0], l[0]);
                bf16_split(v.y, h[1], l[1]);
                bf16_split(v.z, h[2], l[2]);
                bf16_split(v.w, h[3], l[3]);
                int base = o * ASTRIDE + kq * 4;
                *(uint2*)&sA[0][base] = *(uint2*)h;
                *(uint2*)&sA[1][base] = *(uint2*)l;
            }
        }
        // ---- fill B slab: 128 n x 32 k (im2col for conv); stored [n][k]
        {
            int dh = 0, dw = 0, c0;
            if (conv) { int tap = s >> 3; c0 = (s & 7) * 32; dh = tap / 3 - 1; dw = tap % 3 - 1; }
            else c0 = s * 32;
            #pragma unroll
            for (int it = 0; it < 4; it++) {
                int idx = tid + it * 256;       // 1024 = 8 kq x 128 n
                int n = idx & 127, kq = idx >> 7;
                float v[4];
                if (conv) {
                    int pix = n0 + n;
                    int h = (pix >> 6) + dh, w = (pix & 63) + dw;
                    bool ok = (unsigned)h < 64u && (unsigned)w < 64u;
                    int sp = h * 64 + w;
                    const float* p = Xb + (size_t)(c0 + kq * 4) * NPIX + sp;
                    v[0] = ok ? p[0] : 0.f;
                    v[1] = ok ? p[NPIX] : 0.f;
                    v[2] = ok ? p[2 * NPIX] : 0.f;
                    v[3] = ok ? p[3 * NPIX] : 0.f;
                } else {
                    const float* p = Xb + (size_t)(c0 + kq * 4) * NPIX + n0 + n;
                    v[0] = p[0]; v[1] = p[NPIX]; v[2] = p[2 * NPIX]; v[3] = p[3 * NPIX];
                }
                __nv_bfloat16 h[4], l[4];
                #pragma unroll
                for (int j = 0; j < 4; j++) bf16_split(v[j], h[j], l[j]);
                int base = n * ASTRIDE + kq * 4;
                *(uint2*)&sB[0][base] = *(uint2*)h;
                *(uint2*)&sB[1][base] = *(uint2*)l;
            }
        }
        __syncthreads();

        // ---- compute: 2 k16-steps x (2 mt x 8 nt) x 3 split terms
        #pragma unroll
        for (int kt = 0; kt < 2; kt++) {
            uint32_t ah[2][4], al[2][4];
            #pragma unroll
            for (int mt = 0; mt < 2; mt++) {
                int row = mw * 32 + mt * 16 + g;
                int base  = row * ASTRIDE + kt * 16 + t * 2;
                int base8 = (row + 8) * ASTRIDE + kt * 16 + t * 2;
                ah[mt][0] = *(const uint32_t*)&sA[0][base];
                ah[mt][1] = *(const uint32_t*)&sA[0][base8];
                ah[mt][2] = *(const uint32_t*)&sA[0][base + 8];
                ah[mt][3] = *(const uint32_t*)&sA[0][base8 + 8];
                al[mt][0] = *(const uint32_t*)&sA[1][base];
                al[mt][1] = *(const uint32_t*)&sA[1][base8];
                al[mt][2] = *(const uint32_t*)&sA[1][base + 8];
                al[mt][3] = *(const uint32_t*)&sA[1][base8 + 8];
            }
            #pragma unroll
            for (int nt = 0; nt < 8; nt++) {
                int nrow = nw * 64 + nt * 8 + g;
                int kb = nrow * ASTRIDE + kt * 16 + t * 2;
                uint32_t bh[2], bl[2];
                bh[0] = *(const uint32_t*)&sB[0][kb];
                bh[1] = *(const uint32_t*)&sB[0][kb + 8];
                bl[0] = *(const uint32_t*)&sB[1][kb];
                bl[1] = *(const uint32_t*)&sB[1][kb + 8];
                #pragma unroll
                for (int mt = 0; mt < 2; mt++) {
                    mma_bf16(acc[mt][nt], ah[mt], bh);
                    mma_bf16(acc[mt][nt], ah[mt], bl);
                    mma_bf16(acc[mt][nt], al[mt], bh);
                }
            }
        }
        __syncthreads();
    }

    // ---- epilogue: direct stores from fragments (float2 per row-pair)
    #pragma unroll
    for (int mt = 0; mt < 2; mt++) {
        int o_lo = o0 + mw * 32 + mt * 16 + g;
        int o_hi = o_lo + 8;
        float b_lo = bias ? bias[o_lo] : 0.f;
        float b_hi = bias ? bias[o_hi] : 0.f;
        #pragma unroll
        for (int nt = 0; nt < 8; nt++) {
            int n = n0 + nw * 64 + nt * 8 + t * 2;
            size_t off_lo = ((size_t)b * O + o_lo) * NPIX + n;
            size_t off_hi = ((size_t)b * O + o_hi) * NPIX + n;
            float2 v0 = make_float2(acc[mt][nt][0] + b_lo, acc[mt][nt][1] + b_lo);
            float2 v1 = make_float2(acc[mt][nt][2] + b_hi, acc[mt][nt][3] + b_hi);
            if (resid) {
                float2 r0 = *(const float2*)(resid + off_lo);
                float2 r1 = *(const float2*)(resid + off_hi);
                v0.x += r0.x; v0.y += r0.y;
                v1.x += r1.x; v1.y += r1.y;
            }
            *(float2*)(out + off_lo) = v0;
            *(float2*)(out + off_hi) = v1;
        }
    }
}

// ---------------------------------------------------------------------------
// Weight transpose for conv: g_wt[o][tap*256+c] = cpe_w[o][c][tap]
// ---------------------------------------------------------------------------
__global__ void wt_kernel(const float* __restrict__ cpe_w, float* __restrict__ wt)
{
    int o = blockIdx.x, c = threadIdx.x;
    #pragma unroll
    for (int t = 0; t < 9; t++)
        wt[(size_t)o * 2304 + t * 256 + c] = cpe_w[((size_t)o * 256 + c) * 9 + t];
}

// ---------------------------------------------------------------------------
// Softmax row stats over k: per (b',i) max and sum(exp)
// ---------------------------------------------------------------------------
__global__ __launch_bounds__(256) void softmax_stats_kernel(float* __restrict__ stats)
{
    const int row = blockIdx.x;
    const int bp = row >> 5, i = row & 31;
    const int b = bp >> 3, head = bp & 7;
    const float* kptr = g_qkv + ((size_t)b * 3 * CC + CC + head * HD + i) * NPIX;

    __shared__ float red[256];
    const int t = threadIdx.x;

    float m = -1e30f;
    for (int n = t; n < NPIX; n += 256) m = fmaxf(m, kptr[n]);
    red[t] = m; __syncthreads();
    for (int s = 128; s > 0; s >>= 1) { if (t < s) red[t] = fmaxf(red[t], red[t + s]); __syncthreads(); }
    m = red[0];
    __syncthreads();

    float sum = 0.f;
    for (int n = t; n < NPIX; n += 256) sum += __expf(kptr[n] - m);
    red[t] = sum; __syncthreads();
    for (int s = 128; s > 0; s >>= 1) { if (t < s) red[t] += red[t + s]; __syncthreads(); }
    if (t == 0) { stats[row * 2] = m; stats[row * 2 + 1] = red[0]; }
}

// ---------------------------------------------------------------------------
// content_lambda partials: grid (8 chunks, 128 bp), each over 512 n
// ---------------------------------------------------------------------------
__global__ __launch_bounds__(256) void lambda_partial_kernel(const float* __restrict__ stats,
                                                             float* __restrict__ part)
{
    const int chunk = blockIdx.x;
    const int bp = blockIdx.y;
    const int b = bp >> 3, head = bp & 7;
    const float* kbase = g_qkv + ((size_t)b * 3 * CC + CC + head * HD) * NPIX;
    const float* vbase = g_qkv + ((size_t)b * 3 * CC + 2 * CC + head * HD) * NPIX;

    __shared__ float kf[32][129];
    __shared__ float vv[32][129];
    __shared__ float mi[32], si[32];

    const int tid = threadIdx.x;
    if (tid < 32) {
        mi[tid] = stats[(bp * 32 + tid) * 2];
        si[tid] = 1.f / stats[(bp * 32 + tid) * 2 + 1];
    }
    __syncthreads();

    const int o = tid & 31;
    const int ib = (tid >> 5) * 4;
    float acc[4] = {};

    const int nbeg = chunk * 512, nend = nbeg + 512;
    for (int n0 = nbeg; n0 < nend; n0 += 128) {
        for (int idx = tid; idx < 32 * 128; idx += 256) {
            int r = idx >> 7, n = idx & 127;
            kf[r][n] = __expf(kbase[(size_t)r * NPIX + n0 + n] - mi[r]) * si[r];
            vv[r][n] = vbase[(size_t)r * NPIX + n0 + n];
        }
        __syncthreads();
        #pragma unroll 4
        for (int n = 0; n < 128; n++) {
            float vval = vv[o][n];
            #pragma unroll
            for (int j = 0; j < 4; j++) acc[j] += kf[ib + j][n] * vval;
        }
        __syncthreads();
    }
    #pragma unroll
    for (int j = 0; j < 4; j++)
        part[((size_t)bp * 8 + chunk) * 1024 + (ib + j) * 32 + o] = acc[j];
}

__global__ __launch_bounds__(256) void lambda_reduce_kernel(const float* __restrict__ part,
                                                            float* __restrict__ lam)
{
    const int bp = blockIdx.x;
    for (int idx = threadIdx.x; idx < 1024; idx += 256) {
        float s = 0.f;
        #pragma unroll
        for (int c = 0; c < 8; c++) s += part[((size_t)bp * 8 + c) * 1024 + idx];
        lam[(size_t)bp * 1024 + idx] = s;
    }
}

// ---------------------------------------------------------------------------
// Fused content + depthwise 5x5 pos-lambda + combine
// ---------------------------------------------------------------------------
__global__ __launch_bounds__(256) void fused_kernel(const float* __restrict__ lam,
                                                    const float* __restrict__ rel,
                                                    float* __restrict__ res)
{
    const int h0 = blockIdx.x * 4;
    const int o0 = blockIdx.y * 16;
    const int bp = blockIdx.z;
    const int b = bp >> 3, head = bp & 7;

    const float* qbase = g_qkv + ((size_t)b * 3 * CC + head * HD) * NPIX;
    const float* vbase = g_qkv + ((size_t)b * 3 * CC + 2 * CC + head * HD) * NPIX;

    __shared__ float lam_s[32][17];
    __shared__ float rel_s[16][25];
    __shared__ float v_s[16][8][68];

    const int tid = threadIdx.x;
    const float scale = 0.1767766953f;

    for (int idx = tid; idx < 32 * 16; idx += 256) {
        int i = idx >> 4, oo = idx & 15;
        lam_s[i][oo] = lam[(size_t)bp * 1024 + i * 32 + o0 + oo] * scale;
    }
    for (int idx = tid; idx < 16 * 25; idx += 256)
        rel_s[idx / 25][idx % 25] = rel[(o0 + idx / 25) * 25 + idx % 25];
    for (int idx = tid; idx < 16 * 8 * 68; idx += 256) {
        int o = idx / 544;
        int rem = idx % 544;
        int r = rem / 68, c = rem % 68;
        int h = h0 - 2 + r, w = c - 2;
        float val = 0.f;
        if (h >= 0 && h < HH && w >= 0 && w < WW)
            val = vbase[(size_t)(o0 + o) * NPIX + h * WW + w];
        v_s[o][r][c] = val;
    }
    __syncthreads();

    const int wr = tid >> 6;
    const int w = tid & 63;
    const int n = (h0 + wr) * WW + w;

    float qreg[32];
    #pragma unroll
    for (int i = 0; i < 32; i++) qreg[i] = qbase[(size_t)i * NPIX + n];

    float* outb = res + ((size_t)b * CC + head * HD + o0) * NPIX + n;

    #pragma unroll 2
    for (int oo = 0; oo < 16; oo++) {
        float content = 0.f;
        #pragma unroll
        for (int i = 0; i < 32; i++) content += qreg[i] * lam_s[i][oo];
        float pos = 0.f;
        #pragma unroll
        for (int dh = 0; dh < 5; dh++)
            #pragma unroll
            for (int dw = 0; dw < 5; dw++)
                pos += rel_s[oo][dh * 5 + dw] * v_s[oo][wr + dh][w + dw];
        outb[(size_t)oo * NPIX] = content + qreg[o0 + oo] * pos;
    }
}

// ---------------------------------------------------------------------------
extern "C" void kernel_launch(void* const* d_in, const int* in_sizes, int n_in,
                              void* d_out, int out_size)
{
    const float* src   = (const float*)d_in[0];
    const float* rel   = (const float*)d_in[1];
    const float* qkv_w = (const float*)d_in[2];
    const float* cpe_w = (const float*)d_in[3];
    const float* cpe_b = (const float*)d_in[4];
    const float* out_w = (const float*)d_in[5];
    const float* out_b = (const float*)d_in[6];
    float* out = (float*)d_out;

    float *px, *pqkv, *pstats, *plam, *ppart, *pres, *pwt;
    cudaGetSymbolAddress((void**)&px,    g_x);
    cudaGetSymbolAddress((void**)&pqkv,  g_qkv);
    cudaGetSymbolAddress((void**)&pstats,g_stats);
    cudaGetSymbolAddress((void**)&plam,  g_lambda);
    cudaGetSymbolAddress((void**)&ppart, g_lampart);
    cudaGetSymbolAddress((void**)&pres,  g_result);
    cudaGetSymbolAddress((void**)&pwt,   g_wt);

    // 0) transpose conv weights -> [o][tap*256+c]
    wt_kernel<<<256, 256>>>(cpe_w, pwt);
    // 1) CPE conv (implicit GEMM, K=2304) + bias + residual -> x
    gemm_mma<<<dim3(32, 2, 16), 256>>>(pwt, src, px, cpe_b, src, 72, CC, 2304, 1);
    // 2) qkv = qkv_w @ x
    gemm_mma<<<dim3(32, 6, 16), 256>>>(qkv_w, px, pqkv, nullptr, nullptr, 8, 3 * CC, CC, 0);
    // 3) softmax row stats over k
    softmax_stats_kernel<<<4096, 256>>>(pstats);
    // 4) content lambda (split over n, then reduce)
    lambda_partial_kernel<<<dim3(8, 128), 256>>>(pstats, ppart);
    lambda_reduce_kernel<<<128, 256>>>(ppart, plam);
    // 5) fused content + pos-lambda + combine
    fused_kernel<<<dim3(16, 2, 128), 256>>>(plam, rel, pres);
    // 6) output projection
    gemm_mma<<<dim3(32, 2, 16), 256>>>(out_w, pres, out, out_b, nullptr, 8, CC, CC, 0);
}

// round 7
// speedup vs baseline: 3.4835x; 1.0368x over previous
#include <cuda_runtime.h>
#include <cuda_bf16.h>
#include <cstdint>
#include <cstddef>

#define BB 16
#define CC 256
#define HH 64
#define WW 64
#define NHEAD 8
#define HD 32
#define NPIX 4096

// Scratch (device globals; no allocations allowed)
__device__ float g_qkv[(size_t)BB * 3 * CC * NPIX];
__device__ float g_stats[BB * NHEAD * HD * 2];
__device__ float g_lambda[BB * NHEAD * HD * HD];
__device__ float g_lampart[BB * NHEAD * 8 * HD * HD];

// bf16 hi/lo pairs (error-compensated representation)
__device__ __nv_bfloat16 g_srch[(size_t)BB * CC * NPIX];
__device__ __nv_bfloat16 g_srcl[(size_t)BB * CC * NPIX];
__device__ __nv_bfloat16 g_xh[(size_t)BB * CC * NPIX];
__device__ __nv_bfloat16 g_xl[(size_t)BB * CC * NPIX];
__device__ __nv_bfloat16 g_resh[(size_t)BB * CC * NPIX];
__device__ __nv_bfloat16 g_resl[(size_t)BB * CC * NPIX];
__device__ __nv_bfloat16 g_wch[CC * CC * 9];
__device__ __nv_bfloat16 g_wcl[CC * CC * 9];
__device__ __nv_bfloat16 g_wqh[3 * CC * CC];
__device__ __nv_bfloat16 g_wql[3 * CC * CC];
__device__ __nv_bfloat16 g_woh[CC * CC];
__device__ __nv_bfloat16 g_wol[CC * CC];

// ---------------------------------------------------------------------------
__device__ __forceinline__ void bf16_split(float x, __nv_bfloat16& hi, __nv_bfloat16& lo) {
    hi = __float2bfloat16_rn(x);
    lo = __float2bfloat16_rn(x - __bfloat162float(hi));
}
__device__ __forceinline__ uint32_t smem_to_u32(const void* p) {
    uint32_t a;
    asm("{ .reg .u64 t; cvta.to.shared.u64 t, %1; cvt.u32.u64 %0, t; }" : "=r"(a) : "l"(p));
    return a;
}
__device__ __forceinline__ void mma_bf16(float* d, const uint32_t* a, const uint32_t* b) {
    asm volatile(
        "mma.sync.aligned.m16n8k16.row.col.f32.bf16.bf16.f32 "
        "{%0,%1,%2,%3}, {%4,%5,%6,%7}, {%8,%9}, {%0,%1,%2,%3};"
        : "+f"(d[0]), "+f"(d[1]), "+f"(d[2]), "+f"(d[3])
        : "r"(a[0]), "r"(a[1]), "r"(a[2]), "r"(a[3]), "r"(b[0]), "r"(b[1]));
}
#define LDSM4(R, ADDR) \
    asm volatile("ldmatrix.sync.aligned.m8n8.x4.shared.b16 {%0,%1,%2,%3}, [%4];" \
        : "=r"((R)[0]), "=r"((R)[1]), "=r"((R)[2]), "=r"((R)[3]) : "r"(ADDR))
#define LDSM4T(R, ADDR) \
    asm volatile("ldmatrix.sync.aligned.m8n8.x4.trans.shared.b16 {%0,%1,%2,%3}, [%4];" \
        : "=r"((R)[0]), "=r"((R)[1]), "=r"((R)[2]), "=r"((R)[3]) : "r"(ADDR))

// ---------------------------------------------------------------------------
// HMMA GEMM / implicit conv, 3-term bf16 split, pre-split bf16 operands.
// D[b,o,n] = sum_k A[o][k] * B-tile[k][n]; tiles M=128,N=128,Kslab=32.
// A smem [o][40] (ldmatrix), B smem [k][136] (ldmatrix.trans).
// ---------------------------------------------------------------------------
#define ASTR 40
#define BSTR 136
#define ASZB (128 * ASTR * 2)
#define BSZB (32 * BSTR * 2)

__global__ void __launch_bounds__(256, 2)
gemm_mma(const __nv_bfloat16* __restrict__ Ah, const __nv_bfloat16* __restrict__ Al,
         const __nv_bfloat16* __restrict__ Bh, const __nv_bfloat16* __restrict__ Bl,
         int nslabs, int O, int Ktot, int conv,
         float* __restrict__ outF, __nv_bfloat16* __restrict__ outHi,
         __nv_bfloat16* __restrict__ outLo,
         const float* __restrict__ bias, const float* __restrict__ residF)
{
    __shared__ __align__(16) __nv_bfloat16 sA[2][128 * ASTR];
    __shared__ __align__(16) __nv_bfloat16 sB[2][32 * BSTR];

    const int tid  = threadIdx.x;
    const int warp = tid >> 5, lane = tid & 31;
    const int mw = warp & 3, nw = warp >> 2;   // 4(M) x 2(N) warps
    const int g  = lane >> 2, t = lane & 3;
    const int grp = lane >> 3, r = lane & 7;
    const int n0 = blockIdx.x * 128;
    const int o0 = blockIdx.y * 128;
    const int b  = blockIdx.z;

    const uint32_t uA = smem_to_u32(&sA[0][0]);
    const uint32_t uB = smem_to_u32(&sB[0][0]);
    // lane-dependent ldmatrix offsets (elements)
    const int aoff = (((grp & 1) << 3) + r) * ASTR + ((grp >> 1) << 3);
    const int boff = (((grp & 1) << 3) + r) * BSTR + ((grp >> 1) << 3) + nw * 64;

    const __nv_bfloat16* Bhb = Bh + (size_t)b * 256 * NPIX;
    const __nv_bfloat16* Blb = Bl + (size_t)b * 256 * NPIX;

    float acc[2][8][4];
    #pragma unroll
    for (int mt = 0; mt < 2; mt++)
        #pragma unroll
        for (int nt = 0; nt < 8; nt++)
            #pragma unroll
            for (int q = 0; q < 4; q++) acc[mt][nt][q] = 0.f;

    for (int s = 0; s < nslabs; s++) {
        const int k0 = s * 32;
        // ---- A fill: 128 o x 32 k, straight bf16 copy
        #pragma unroll
        for (int it = 0; it < 2; it++) {
            int idx = tid + it * 256;           // 512 = 128 o x 4 q(8k)
            int q = idx & 3, o = idx >> 2;
            size_t goff = (size_t)(o0 + o) * Ktot + k0 + q * 8;
            *(uint4*)&sA[0][o * ASTR + q * 8] = *(const uint4*)(Ah + goff);
            *(uint4*)&sA[1][o * ASTR + q * 8] = *(const uint4*)(Al + goff);
        }
        // ---- B fill: 32 k x 128 n
        if (!conv) {
            const int c0 = k0;
            #pragma unroll
            for (int it = 0; it < 2; it++) {
                int idx = tid + it * 256;       // 512 = 32 k x 16 groups
                int a = idx & 15, k = idx >> 4;
                size_t goff = (size_t)(c0 + k) * NPIX + n0 + a * 8;
                *(uint4*)&sB[0][k * BSTR + a * 8] = *(const uint4*)(Bhb + goff);
                *(uint4*)&sB[1][k * BSTR + a * 8] = *(const uint4*)(Blb + goff);
            }
        } else {
            const int tap = s >> 3, c0 = (s & 7) * 32;
            const int dh = tap / 3 - 1, dw = tap % 3 - 1;
            #pragma unroll
            for (int it = 0; it < 2; it++) {
                int idx = tid + it * 256;
                int a = idx & 15, k = idx >> 4;
                int pixb = n0 + a * 8;
                int h = pixb >> 6, w0 = pixb & 63;
                int hs = h + dh;
                bool okh = (unsigned)hs < 64u;
                #pragma unroll
                for (int arr = 0; arr < 2; arr++) {
                    const __nv_bfloat16* rowp =
                        (arr ? Blb : Bhb) + (size_t)(c0 + k) * NPIX + hs * 64;
                    uint4 v = make_uint4(0, 0, 0, 0);
                    if (okh) v = *(const uint4*)(rowp + w0);
                    uint4 o4;
                    if (dw == 0) {
                        o4 = v;
                    } else if (dw == 1) {
                        uint32_t ex = (okh && w0 + 8 < 64)
                            ? (uint32_t)*(const unsigned short*)(rowp + w0 + 8) : 0u;
                        o4.x = (v.x >> 16) | (v.y << 16);
                        o4.y = (v.y >> 16) | (v.z << 16);
                        o4.z = (v.z >> 16) | (v.w << 16);
                        o4.w = (v.w >> 16) | (ex << 16);
                    } else {
                        uint32_t ex = (okh && w0 > 0)
                            ? (uint32_t)*(const unsigned short*)(rowp + w0 - 1) : 0u;
                        o4.x = (v.x << 16) | ex;
                        o4.y = (v.y << 16) | (v.x >> 16);
                        o4.z = (v.z << 16) | (v.y >> 16);
                        o4.w = (v.w << 16) | (v.z >> 16);
                    }
                    *(uint4*)&sB[arr][k * BSTR + a * 8] = o4;
                }
            }
        }
        __syncthreads();

        // ---- compute: ldmatrix fragments + 96 HMMA
        #pragma unroll
        for (int kt = 0; kt < 2; kt++) {
            uint32_t ah[2][4], al[2][4];
            #pragma unroll
            for (int mt = 0; mt < 2; mt++) {
                uint32_t ad = uA + 2 * (aoff + (mw * 32 + mt * 16) * ASTR + kt * 16);
                LDSM4(ah[mt], ad);
                LDSM4(al[mt], ad + ASZB);
            }
            #pragma unroll
            for (int ntp = 0; ntp < 4; ntp++) {
                uint32_t bd = uB + 2 * (boff + ntp * 16 + kt * 16 * BSTR);
                uint32_t bh[4], bl[4];
                LDSM4T(bh, bd);
                LDSM4T(bl, bd + BSZB);
                #pragma unroll
                for (int mt = 0; mt < 2; mt++) {
                    mma_bf16(acc[mt][ntp * 2],     ah[mt], &bh[0]);
                    mma_bf16(acc[mt][ntp * 2],     ah[mt], &bl[0]);
                    mma_bf16(acc[mt][ntp * 2],     al[mt], &bh[0]);
                    mma_bf16(acc[mt][ntp * 2 + 1], ah[mt], &bh[2]);
                    mma_bf16(acc[mt][ntp * 2 + 1], ah[mt], &bl[2]);
                    mma_bf16(acc[mt][ntp * 2 + 1], al[mt], &bh[2]);
                }
            }
        }
        __syncthreads();
    }

    // ---- epilogue
    #pragma unroll
    for (int mt = 0; mt < 2; mt++) {
        int o_lo = o0 + mw * 32 + mt * 16 + g;
        int o_hi = o_lo + 8;
        float b_lo = bias ? bias[o_lo] : 0.f;
        float b_hi = bias ? bias[o_hi] : 0.f;
        #pragma unroll
        for (int nt = 0; nt < 8; nt++) {
            int n = n0 + nw * 64 + nt * 8 + t * 2;
            size_t off_lo = ((size_t)b * O + o_lo) * NPIX + n;
            size_t off_hi = ((size_t)b * O + o_hi) * NPIX + n;
            float2 v0 = make_float2(acc[mt][nt][0] + b_lo, acc[mt][nt][1] + b_lo);
            float2 v1 = make_float2(acc[mt][nt][2] + b_hi, acc[mt][nt][3] + b_hi);
            if (outF) {
                *(float2*)(outF + off_lo) = v0;
                *(float2*)(outF + off_hi) = v1;
            } else {
                float2 r0 = *(const float2*)(residF + off_lo);
                float2 r1 = *(const float2*)(residF + off_hi);
                v0.x += r0.x; v0.y += r0.y;
                v1.x += r1.x; v1.y += r1.y;
                __nv_bfloat162 h0, l0, h1, l1;
                bf16_split(v0.x, h0.x, l0.x); bf16_split(v0.y, h0.y, l0.y);
                bf16_split(v1.x, h1.x, l1.x); bf16_split(v1.y, h1.y, l1.y);
                *(__nv_bfloat162*)(outHi + off_lo) = h0;
                *(__nv_bfloat162*)(outLo + off_lo) = l0;
                *(__nv_bfloat162*)(outHi + off_hi) = h1;
                *(__nv_bfloat162*)(outLo + off_hi) = l1;
            }
        }
    }
}

// ---------------------------------------------------------------------------
// Prep kernels
// ---------------------------------------------------------------------------
__global__ void split_pass(const float* __restrict__ in, __nv_bfloat16* __restrict__ hi,
                           __nv_bfloat16* __restrict__ lo, int n4)
{
    int idx = blockIdx.x * blockDim.x + threadIdx.x;
    if (idx >= n4) return;
    float4 v = ((const float4*)in)[idx];
    __nv_bfloat16 h[4], l[4];
    bf16_split(v.x, h[0], l[0]);
    bf16_split(v.y, h[1], l[1]);
    bf16_split(v.z, h[2], l[2]);
    bf16_split(v.w, h[3], l[3]);
    *(uint2*)(hi + (size_t)idx * 4) = *(uint2*)h;
    *(uint2*)(lo + (size_t)idx * 4) = *(uint2*)l;
}

__global__ void wtc_kernel(const float* __restrict__ cpe_w,
                           __nv_bfloat16* __restrict__ wh, __nv_bfloat16* __restrict__ wl)
{
    int o = blockIdx.x, c = threadIdx.x;
    #pragma unroll
    for (int tp = 0; tp < 9; tp++) {
        float v = cpe_w[((size_t)o * 256 + c) * 9 + tp];
        __nv_bfloat16 h, l;
        bf16_split(v, h, l);
        wh[(size_t)o * 2304 + tp * 256 + c] = h;
        wl[(size_t)o * 2304 + tp * 256 + c] = l;
    }
}

// ---------------------------------------------------------------------------
// Softmax row stats
// ---------------------------------------------------------------------------
__global__ __launch_bounds__(256) void softmax_stats_kernel(float* __restrict__ stats)
{
    const int row = blockIdx.x;
    const int bp = row >> 5, i = row & 31;
    const int b = bp >> 3, head = bp & 7;
    const float* kptr = g_qkv + ((size_t)b * 3 * CC + CC + head * HD + i) * NPIX;

    __shared__ float red[256];
    const int t = threadIdx.x;

    float m = -1e30f;
    for (int n = t; n < NPIX; n += 256) m = fmaxf(m, kptr[n]);
    red[t] = m; __syncthreads();
    for (int s = 128; s > 0; s >>= 1) { if (t < s) red[t] = fmaxf(red[t], red[t + s]); __syncthreads(); }
    m = red[0];
    __syncthreads();

    float sum = 0.f;
    for (int n = t; n < NPIX; n += 256) sum += __expf(kptr[n] - m);
    red[t] = sum; __syncthreads();
    for (int s = 128; s > 0; s >>= 1) { if (t < s) red[t] += red[t + s]; __syncthreads(); }
    if (t == 0) { stats[row * 2] = m; stats[row * 2 + 1] = red[0]; }
}

// ---------------------------------------------------------------------------
// content_lambda partials + reduce
// ---------------------------------------------------------------------------
__global__ __launch_bounds__(256) void lambda_partial_kernel(const float* __restrict__ stats,
                                                             float* __restrict__ part)
{
    const int chunk = blockIdx.x;
    const int bp = blockIdx.y;
    const int b = bp >> 3, head = bp & 7;
    const float* kbase = g_qkv + ((size_t)b * 3 * CC + CC + head * HD) * NPIX;
    const float* vbase = g_qkv + ((size_t)b * 3 * CC + 2 * CC + head * HD) * NPIX;

    __shared__ float kf[32][129];
    __shared__ float vv[32][129];
    __shared__ float mi[32], si[32];

    const int tid = threadIdx.x;
    if (tid < 32) {
        mi[tid] = stats[(bp * 32 + tid) * 2];
        si[tid] = 1.f / stats[(bp * 32 + tid) * 2 + 1];
    }
    __syncthreads();

    const int o = tid & 31;
    const int ib = (tid >> 5) * 4;
    float acc[4] = {};

    const int nbeg = chunk * 512, nend = nbeg + 512;
    for (int n0 = nbeg; n0 < nend; n0 += 128) {
        for (int idx = tid; idx < 32 * 128; idx += 256) {
            int rr = idx >> 7, n = idx & 127;
            kf[rr][n] = __expf(kbase[(size_t)rr * NPIX + n0 + n] - mi[rr]) * si[rr];
            vv[rr][n] = vbase[(size_t)rr * NPIX + n0 + n];
        }
        __syncthreads();
        #pragma unroll 4
        for (int n = 0; n < 128; n++) {
            float vval = vv[o][n];
            #pragma unroll
            for (int j = 0; j < 4; j++) acc[j] += kf[ib + j][n] * vval;
        }
        __syncthreads();
    }
    #pragma unroll
    for (int j = 0; j < 4; j++)
        part[((size_t)bp * 8 + chunk) * 1024 + (ib + j) * 32 + o] = acc[j];
}

__global__ __launch_bounds__(256) void lambda_reduce_kernel(const float* __restrict__ part,
                                                            float* __restrict__ lam)
{
    const int bp = blockIdx.x;
    for (int idx = threadIdx.x; idx < 1024; idx += 256) {
        float s = 0.f;
        #pragma unroll
        for (int c = 0; c < 8; c++) s += part[((size_t)bp * 8 + c) * 1024 + idx];
        lam[(size_t)bp * 1024 + idx] = s;
    }
}

// ---------------------------------------------------------------------------
// Fused content + depthwise 5x5 pos-lambda + combine; writes bf16 hi/lo
// ---------------------------------------------------------------------------
__global__ __launch_bounds__(256) void fused_kernel(const float* __restrict__ lam,
                                                    const float* __restrict__ rel,
                                                    __nv_bfloat16* __restrict__ resh,
                                                    __nv_bfloat16* __restrict__ resl)
{
    const int h0 = blockIdx.x * 4;
    const int o0 = blockIdx.y * 16;
    const int bp = blockIdx.z;
    const int b = bp >> 3, head = bp & 7;

    const float* qbase = g_qkv + ((size_t)b * 3 * CC + head * HD) * NPIX;
    const float* vbase = g_qkv + ((size_t)b * 3 * CC + 2 * CC + head * HD) * NPIX;

    __shared__ float lam_s[32][17];
    __shared__ float rel_s[16][25];
    __shared__ float v_s[16][8][68];

    const int tid = threadIdx.x;
    const float scale = 0.1767766953f;

    for (int idx = tid; idx < 32 * 16; idx += 256) {
        int i = idx >> 4, oo = idx & 15;
        lam_s[i][oo] = lam[(size_t)bp * 1024 + i * 32 + o0 + oo] * scale;
    }
    for (int idx = tid; idx < 16 * 25; idx += 256)
        rel_s[idx / 25][idx % 25] = rel[(o0 + idx / 25) * 25 + idx % 25];
    for (int idx = tid; idx < 16 * 8 * 68; idx += 256) {
        int o = idx / 544;
        int rem = idx % 544;
        int rr = rem / 68, c = rem % 68;
        int h = h0 - 2 + rr, w = c - 2;
        float val = 0.f;
        if (h >= 0 && h < HH && w >= 0 && w < WW)
            val = vbase[(size_t)(o0 + o) * NPIX + h * WW + w];
        v_s[o][rr][c] = val;
    }
    __syncthreads();

    const int wr = tid >> 6;
    const int w = tid & 63;
    const int n = (h0 + wr) * WW + w;

    float qreg[32];
    #pragma unroll
    for (int i = 0; i < 32; i++) qreg[i] = qbase[(size_t)i * NPIX + n];

    const size_t obase = ((size_t)b * CC + head * HD + o0) * NPIX + n;

    #pragma unroll 2
    for (int oo = 0; oo < 16; oo++) {
        float content = 0.f;
        #pragma unroll
        for (int i = 0; i < 32; i++) content += qreg[i] * lam_s[i][oo];
        float pos = 0.f;
        #pragma unroll
        for (int dh = 0; dh < 5; dh++)
            #pragma unroll
            for (int dw = 0; dw < 5; dw++)
                pos += rel_s[oo][dh * 5 + dw] * v_s[oo][wr + dh][w + dw];
        float val = content + qreg[o0 + oo] * pos;
        __nv_bfloat16 h, l;
        bf16_split(val, h, l);
        resh[obase + (size_t)oo * NPIX] = h;
        resl[obase + (size_t)oo * NPIX] = l;
    }
}

// ---------------------------------------------------------------------------
extern "C" void kernel_launch(void* const* d_in, const int* in_sizes, int n_in,
                              void* d_out, int out_size)
{
    const float* src   = (const float*)d_in[0];
    const float* rel   = (const float*)d_in[1];
    const float* qkv_w = (const float*)d_in[2];
    const float* cpe_w = (const float*)d_in[3];
    const float* cpe_b = (const float*)d_in[4];
    const float* out_w = (const float*)d_in[5];
    const float* out_b = (const float*)d_in[6];
    float* out = (float*)d_out;

    float *pqkv, *pstats, *plam, *ppart;
    __nv_bfloat16 *psrch, *psrcl, *pxh, *pxl, *presh, *presl;
    __nv_bfloat16 *pwch, *pwcl, *pwqh, *pwql, *pwoh, *pwol;
    cudaGetSymbolAddress((void**)&pqkv,  g_qkv);
    cudaGetSymbolAddress((void**)&pstats,g_stats);
    cudaGetSymbolAddress((void**)&plam,  g_lambda);
    cudaGetSymbolAddress((void**)&ppart, g_lampart);
    cudaGetSymbolAddress((void**)&psrch, g_srch);
    cudaGetSymbolAddress((void**)&psrcl, g_srcl);
    cudaGetSymbolAddress((void**)&pxh,   g_xh);
    cudaGetSymbolAddress((void**)&pxl,   g_xl);
    cudaGetSymbolAddress((void**)&presh, g_resh);
    cudaGetSymbolAddress((void**)&presl, g_resl);
    cudaGetSymbolAddress((void**)&pwch,  g_wch);
    cudaGetSymbolAddress((void**)&pwcl,  g_wcl);
    cudaGetSymbolAddress((void**)&pwqh,  g_wqh);
    cudaGetSymbolAddress((void**)&pwql,  g_wql);
    cudaGetSymbolAddress((void**)&pwoh,  g_woh);
    cudaGetSymbolAddress((void**)&pwol,  g_wol);

    // 0) pre-split operands to bf16 hi/lo
    split_pass<<<16384, 256>>>(src, psrch, psrcl, BB * CC * NPIX / 4);
    wtc_kernel<<<256, 256>>>(cpe_w, pwch, pwcl);
    split_pass<<<192, 256>>>(qkv_w, pwqh, pwql, 3 * CC * CC / 4);
    split_pass<<<64, 256>>>(out_w, pwoh, pwol, CC * CC / 4);

    // 1) CPE conv (implicit GEMM K=2304) + bias + residual -> x (bf16 hi/lo)
    gemm_mma<<<dim3(32, 2, 16), 256>>>(pwch, pwcl, psrch, psrcl, 72, CC, 2304, 1,
                                       nullptr, pxh, pxl, cpe_b, src);
    // 2) qkv = qkv_w @ x -> fp32
    gemm_mma<<<dim3(32, 6, 16), 256>>>(pwqh, pwql, pxh, pxl, 8, 3 * CC, CC, 0,
                                       pqkv, nullptr, nullptr, nullptr, nullptr);
    // 3) softmax stats
    softmax_stats_kernel<<<4096, 256>>>(pstats);
    // 4) content lambda
    lambda_partial_kernel<<<dim3(8, 128), 256>>>(pstats, ppart);
    lambda_reduce_kernel<<<128, 256>>>(ppart, plam);
    // 5) fused content + pos-lambda -> result (bf16 hi/lo)
    fused_kernel<<<dim3(16, 2, 128), 256>>>(plam, rel, presh, presl);
    // 6) output projection -> d_out fp32
    gemm_mma<<<dim3(32, 2, 16), 256>>>(pwoh, pwol, presh, presl, 8, CC, CC, 0,
                                       out, nullptr, nullptr, out_b, nullptr);
}

// round 8
// speedup vs baseline: 3.6292x; 1.0418x over previous
#include <cuda_runtime.h>
#include <cuda_bf16.h>
#include <cstdint>
#include <cstddef>

#define BB 16
#define CC 256
#define HH 64
#define WW 64
#define NHEAD 8
#define HD 32
#define NPIX 4096

// Scratch (device globals; no allocations allowed)
__device__ float g_qkv[(size_t)BB * 3 * CC * NPIX];
__device__ float g_stats[BB * NHEAD * HD * 2];
__device__ float g_lambda[BB * NHEAD * HD * HD];
__device__ float g_lampart[BB * NHEAD * 8 * HD * HD];

// bf16 hi/lo pairs (error-compensated representation)
__device__ __nv_bfloat16 g_srch[(size_t)BB * CC * NPIX];
__device__ __nv_bfloat16 g_srcl[(size_t)BB * CC * NPIX];
__device__ __nv_bfloat16 g_xh[(size_t)BB * CC * NPIX];
__device__ __nv_bfloat16 g_xl[(size_t)BB * CC * NPIX];
__device__ __nv_bfloat16 g_resh[(size_t)BB * CC * NPIX];
__device__ __nv_bfloat16 g_resl[(size_t)BB * CC * NPIX];
__device__ __nv_bfloat16 g_wch[CC * CC * 9];
__device__ __nv_bfloat16 g_wcl[CC * CC * 9];
__device__ __nv_bfloat16 g_wqh[3 * CC * CC];
__device__ __nv_bfloat16 g_wql[3 * CC * CC];
__device__ __nv_bfloat16 g_woh[CC * CC];
__device__ __nv_bfloat16 g_wol[CC * CC];

// ---------------------------------------------------------------------------
__device__ __forceinline__ void bf16_split(float x, __nv_bfloat16& hi, __nv_bfloat16& lo) {
    hi = __float2bfloat16_rn(x);
    lo = __float2bfloat16_rn(x - __bfloat162float(hi));
}
__device__ __forceinline__ uint32_t smem_to_u32(const void* p) {
    uint32_t a;
    asm("{ .reg .u64 t; cvta.to.shared.u64 t, %1; cvt.u32.u64 %0, t; }" : "=r"(a) : "l"(p));
    return a;
}
__device__ __forceinline__ void mma_bf16(float* d, const uint32_t* a, const uint32_t* b) {
    asm volatile(
        "mma.sync.aligned.m16n8k16.row.col.f32.bf16.bf16.f32 "
        "{%0,%1,%2,%3}, {%4,%5,%6,%7}, {%8,%9}, {%0,%1,%2,%3};"
        : "+f"(d[0]), "+f"(d[1]), "+f"(d[2]), "+f"(d[3])
        : "r"(a[0]), "r"(a[1]), "r"(a[2]), "r"(a[3]), "r"(b[0]), "r"(b[1]));
}
#define LDSM4(R, ADDR) \
    asm volatile("ldmatrix.sync.aligned.m8n8.x4.shared.b16 {%0,%1,%2,%3}, [%4];" \
        : "=r"((R)[0]), "=r"((R)[1]), "=r"((R)[2]), "=r"((R)[3]) : "r"(ADDR))
#define LDSM4T(R, ADDR) \
    asm volatile("ldmatrix.sync.aligned.m8n8.x4.trans.shared.b16 {%0,%1,%2,%3}, [%4];" \
        : "=r"((R)[0]), "=r"((R)[1]), "=r"((R)[2]), "=r"((R)[3]) : "r"(ADDR))

// ---------------------------------------------------------------------------
// HMMA GEMM / implicit conv, 3-term bf16 split, pre-split bf16 operands,
// 2-stage double-buffered SMEM pipeline (fill s+1 overlaps MMA of s).
// D[b,o,n] = sum_k A[o][k] * B-tile[k][n]; tiles M=128,N=128,Kslab=32.
// ---------------------------------------------------------------------------
#define ASTR 40
#define BSTR 136
#define A_ELEMS (128 * ASTR)
#define B_ELEMS (32 * BSTR)
#define ASZB (A_ELEMS * 2)
#define BSZB (B_ELEMS * 2)
#define STAGE_ELEMS (2 * A_ELEMS + 2 * B_ELEMS)
#define STAGE_BYTES (STAGE_ELEMS * 2)
#define SMEM_BYTES (2 * STAGE_BYTES)

__global__ void __launch_bounds__(256, 2)
gemm_mma(const __nv_bfloat16* __restrict__ Ah, const __nv_bfloat16* __restrict__ Al,
         const __nv_bfloat16* __restrict__ Bh, const __nv_bfloat16* __restrict__ Bl,
         int nslabs, int O, int Ktot, int conv,
         float* __restrict__ outF, __nv_bfloat16* __restrict__ outHi,
         __nv_bfloat16* __restrict__ outLo,
         const float* __restrict__ bias, const float* __restrict__ residF)
{
    extern __shared__ __align__(16) __nv_bfloat16 smem[];

    const int tid  = threadIdx.x;
    const int warp = tid >> 5, lane = tid & 31;
    const int mw = warp & 3, nw = warp >> 2;   // 4(M) x 2(N) warps
    const int g  = lane >> 2, t = lane & 3;
    const int grp = lane >> 3, r = lane & 7;
    const int n0 = blockIdx.x * 128;
    const int o0 = blockIdx.y * 128;
    const int b  = blockIdx.z;

    const uint32_t uS = smem_to_u32(smem);
    const int aoff = (((grp & 1) << 3) + r) * ASTR + ((grp >> 1) << 3);
    const int boff = (((grp & 1) << 3) + r) * BSTR + ((grp >> 1) << 3) + nw * 64;

    const __nv_bfloat16* Bhb = Bh + (size_t)b * 256 * NPIX;
    const __nv_bfloat16* Blb = Bl + (size_t)b * 256 * NPIX;

    float acc[2][8][4];
    #pragma unroll
    for (int mt = 0; mt < 2; mt++)
        #pragma unroll
        for (int nt = 0; nt < 8; nt++)
            #pragma unroll
            for (int q = 0; q < 4; q++) acc[mt][nt][q] = 0.f;

    auto fill = [&](int s, int st) {
        __nv_bfloat16* pA0 = smem + st * STAGE_ELEMS;
        __nv_bfloat16* pA1 = pA0 + A_ELEMS;
        __nv_bfloat16* pB0 = pA0 + 2 * A_ELEMS;
        __nv_bfloat16* pB1 = pB0 + B_ELEMS;
        const int k0 = s * 32;
        // A: 128 o x 32 k
        #pragma unroll
        for (int it = 0; it < 2; it++) {
            int idx = tid + it * 256;
            int q = idx & 3, o = idx >> 2;
            size_t goff = (size_t)(o0 + o) * Ktot + k0 + q * 8;
            *(uint4*)&pA0[o * ASTR + q * 8] = *(const uint4*)(Ah + goff);
            *(uint4*)&pA1[o * ASTR + q * 8] = *(const uint4*)(Al + goff);
        }
        // B: 32 k x 128 n
        if (!conv) {
            #pragma unroll
            for (int it = 0; it < 2; it++) {
                int idx = tid + it * 256;
                int a = idx & 15, k = idx >> 4;
                size_t goff = (size_t)(k0 + k) * NPIX + n0 + a * 8;
                *(uint4*)&pB0[k * BSTR + a * 8] = *(const uint4*)(Bhb + goff);
                *(uint4*)&pB1[k * BSTR + a * 8] = *(const uint4*)(Blb + goff);
            }
        } else {
            const int tap = s >> 3, c0 = (s & 7) * 32;
            const int dh = tap / 3 - 1, dw = tap % 3 - 1;
            #pragma unroll
            for (int it = 0; it < 2; it++) {
                int idx = tid + it * 256;
                int a = idx & 15, k = idx >> 4;
                int pixb = n0 + a * 8;
                int h = pixb >> 6, w0 = pixb & 63;
                int hs = h + dh;
                bool okh = (unsigned)hs < 64u;
                #pragma unroll
                for (int arr = 0; arr < 2; arr++) {
                    const __nv_bfloat16* rowp =
                        (arr ? Blb : Bhb) + (size_t)(c0 + k) * NPIX + hs * 64;
                    uint4 v = make_uint4(0, 0, 0, 0);
                    if (okh) v = *(const uint4*)(rowp + w0);
                    uint4 o4;
                    if (dw == 0) {
                        o4 = v;
                    } else if (dw == 1) {
                        uint32_t ex = (okh && w0 + 8 < 64)
                            ? (uint32_t)*(const unsigned short*)(rowp + w0 + 8) : 0u;
                        o4.x = (v.x >> 16) | (v.y << 16);
                        o4.y = (v.y >> 16) | (v.z << 16);
                        o4.z = (v.z >> 16) | (v.w << 16);
                        o4.w = (v.w >> 16) | (ex << 16);
                    } else {
                        uint32_t ex = (okh && w0 > 0)
                            ? (uint32_t)*(const unsigned short*)(rowp + w0 - 1) : 0u;
                        o4.x = (v.x << 16) | ex;
                        o4.y = (v.y << 16) | (v.x >> 16);
                        o4.z = (v.z << 16) | (v.y >> 16);
                        o4.w = (v.w << 16) | (v.z >> 16);
                    }
                    __nv_bfloat16* dst = arr ? pB1 : pB0;
                    *(uint4*)&dst[k * BSTR + a * 8] = o4;
                }
            }
        }
    };

    fill(0, 0);
    __syncthreads();

    for (int s = 0; s < nslabs; s++) {
        const int cur = s & 1;
        if (s + 1 < nslabs) fill(s + 1, cur ^ 1);

        const uint32_t uAst = uS + cur * STAGE_BYTES;
        const uint32_t uBst = uAst + 2 * ASZB;
        #pragma unroll
        for (int kt = 0; kt < 2; kt++) {
            uint32_t ah[2][4], al[2][4];
            #pragma unroll
            for (int mt = 0; mt < 2; mt++) {
                uint32_t ad = uAst + 2 * (aoff + (mw * 32 + mt * 16) * ASTR + kt * 16);
                LDSM4(ah[mt], ad);
                LDSM4(al[mt], ad + ASZB);
            }
            #pragma unroll
            for (int ntp = 0; ntp < 4; ntp++) {
                uint32_t bd = uBst + 2 * (boff + ntp * 16 + kt * 16 * BSTR);
                uint32_t bh[4], bl[4];
                LDSM4T(bh, bd);
                LDSM4T(bl, bd + BSZB);
                #pragma unroll
                for (int mt = 0; mt < 2; mt++) {
                    mma_bf16(acc[mt][ntp * 2],     ah[mt], &bh[0]);
                    mma_bf16(acc[mt][ntp * 2],     ah[mt], &bl[0]);
                    mma_bf16(acc[mt][ntp * 2],     al[mt], &bh[0]);
                    mma_bf16(acc[mt][ntp * 2 + 1], ah[mt], &bh[2]);
                    mma_bf16(acc[mt][ntp * 2 + 1], ah[mt], &bl[2]);
                    mma_bf16(acc[mt][ntp * 2 + 1], al[mt], &bh[2]);
                }
            }
        }
        __syncthreads();
    }

    // ---- epilogue
    #pragma unroll
    for (int mt = 0; mt < 2; mt++) {
        int o_lo = o0 + mw * 32 + mt * 16 + g;
        int o_hi = o_lo + 8;
        float b_lo = bias ? bias[o_lo] : 0.f;
        float b_hi = bias ? bias[o_hi] : 0.f;
        #pragma unroll
        for (int nt = 0; nt < 8; nt++) {
            int n = n0 + nw * 64 + nt * 8 + t * 2;
            size_t off_lo = ((size_t)b * O + o_lo) * NPIX + n;
            size_t off_hi = ((size_t)b * O + o_hi) * NPIX + n;
            float2 v0 = make_float2(acc[mt][nt][0] + b_lo, acc[mt][nt][1] + b_lo);
            float2 v1 = make_float2(acc[mt][nt][2] + b_hi, acc[mt][nt][3] + b_hi);
            if (outF) {
                *(float2*)(outF + off_lo) = v0;
                *(float2*)(outF + off_hi) = v1;
            } else {
                float2 r0 = *(const float2*)(residF + off_lo);
                float2 r1 = *(const float2*)(residF + off_hi);
                v0.x += r0.x; v0.y += r0.y;
                v1.x += r1.x; v1.y += r1.y;
                __nv_bfloat162 h0, l0, h1, l1;
                bf16_split(v0.x, h0.x, l0.x); bf16_split(v0.y, h0.y, l0.y);
                bf16_split(v1.x, h1.x, l1.x); bf16_split(v1.y, h1.y, l1.y);
                *(__nv_bfloat162*)(outHi + off_lo) = h0;
                *(__nv_bfloat162*)(outLo + off_lo) = l0;
                *(__nv_bfloat162*)(outHi + off_hi) = h1;
                *(__nv_bfloat162*)(outLo + off_hi) = l1;
            }
        }
    }
}

// ---------------------------------------------------------------------------
// Prep kernels
// ---------------------------------------------------------------------------
__global__ void split_pass(const float* __restrict__ in, __nv_bfloat16* __restrict__ hi,
                           __nv_bfloat16* __restrict__ lo, int n4)
{
    int idx = blockIdx.x * blockDim.x + threadIdx.x;
    if (idx >= n4) return;
    float4 v = ((const float4*)in)[idx];
    __nv_bfloat16 h[4], l[4];
    bf16_split(v.x, h[0], l[0]);
    bf16_split(v.y, h[1], l[1]);
    bf16_split(v.z, h[2], l[2]);
    bf16_split(v.w, h[3], l[3]);
    *(uint2*)(hi + (size_t)idx * 4) = *(uint2*)h;
    *(uint2*)(lo + (size_t)idx * 4) = *(uint2*)l;
}

__global__ void wtc_kernel(const float* __restrict__ cpe_w,
                           __nv_bfloat16* __restrict__ wh, __nv_bfloat16* __restrict__ wl)
{
    int o = blockIdx.x, c = threadIdx.x;
    #pragma unroll
    for (int tp = 0; tp < 9; tp++) {
        float v = cpe_w[((size_t)o * 256 + c) * 9 + tp];
        __nv_bfloat16 h, l;
        bf16_split(v, h, l);
        wh[(size_t)o * 2304 + tp * 256 + c] = h;
        wl[(size_t)o * 2304 + tp * 256 + c] = l;
    }
}

// ---------------------------------------------------------------------------
// Softmax row stats
// ---------------------------------------------------------------------------
__global__ __launch_bounds__(256) void softmax_stats_kernel(float* __restrict__ stats)
{
    const int row = blockIdx.x;
    const int bp = row >> 5, i = row & 31;
    const int b = bp >> 3, head = bp & 7;
    const float* kptr = g_qkv + ((size_t)b * 3 * CC + CC + head * HD + i) * NPIX;

    __shared__ float red[256];
    const int t = threadIdx.x;

    float m = -1e30f;
    for (int n = t; n < NPIX; n += 256) m = fmaxf(m, kptr[n]);
    red[t] = m; __syncthreads();
    for (int s = 128; s > 0; s >>= 1) { if (t < s) red[t] = fmaxf(red[t], red[t + s]); __syncthreads(); }
    m = red[0];
    __syncthreads();

    float sum = 0.f;
    for (int n = t; n < NPIX; n += 256) sum += __expf(kptr[n] - m);
    red[t] = sum; __syncthreads();
    for (int s = 128; s > 0; s >>= 1) { if (t < s) red[t] += red[t + s]; __syncthreads(); }
    if (t == 0) { stats[row * 2] = m; stats[row * 2 + 1] = red[0]; }
}

// ---------------------------------------------------------------------------
// content_lambda partials + reduce
// ---------------------------------------------------------------------------
__global__ __launch_bounds__(256) void lambda_partial_kernel(const float* __restrict__ stats,
                                                             float* __restrict__ part)
{
    const int chunk = blockIdx.x;
    const int bp = blockIdx.y;
    const int b = bp >> 3, head = bp & 7;
    const float* kbase = g_qkv + ((size_t)b * 3 * CC + CC + head * HD) * NPIX;
    const float* vbase = g_qkv + ((size_t)b * 3 * CC + 2 * CC + head * HD) * NPIX;

    __shared__ float kf[32][129];
    __shared__ float vv[32][129];
    __shared__ float mi[32], si[32];

    const int tid = threadIdx.x;
    if (tid < 32) {
        mi[tid] = stats[(bp * 32 + tid) * 2];
        si[tid] = 1.f / stats[(bp * 32 + tid) * 2 + 1];
    }
    __syncthreads();

    const int o = tid & 31;
    const int ib = (tid >> 5) * 4;
    float acc[4] = {};

    const int nbeg = chunk * 512, nend = nbeg + 512;
    for (int n0 = nbeg; n0 < nend; n0 += 128) {
        for (int idx = tid; idx < 32 * 128; idx += 256) {
            int rr = idx >> 7, n = idx & 127;
            kf[rr][n] = __expf(kbase[(size_t)rr * NPIX + n0 + n] - mi[rr]) * si[rr];
            vv[rr][n] = vbase[(size_t)rr * NPIX + n0 + n];
        }
        __syncthreads();
        #pragma unroll 4
        for (int n = 0; n < 128; n++) {
            float vval = vv[o][n];
            #pragma unroll
            for (int j = 0; j < 4; j++) acc[j] += kf[ib + j][n] * vval;
        }
        __syncthreads();
    }
    #pragma unroll
    for (int j = 0; j < 4; j++)
        part[((size_t)bp * 8 + chunk) * 1024 + (ib + j) * 32 + o] = acc[j];
}

__global__ __launch_bounds__(256) void lambda_reduce_kernel(const float* __restrict__ part,
                                                            float* __restrict__ lam)
{
    const int bp = blockIdx.x;
    for (int idx = threadIdx.x; idx < 1024; idx += 256) {
        float s = 0.f;
        #pragma unroll
        for (int c = 0; c < 8; c++) s += part[((size_t)bp * 8 + c) * 1024 + idx];
        lam[(size_t)bp * 1024 + idx] = s;
    }
}

// ---------------------------------------------------------------------------
// Fused content + depthwise 5x5 pos-lambda + combine; writes bf16 hi/lo
// ---------------------------------------------------------------------------
__global__ __launch_bounds__(256) void fused_kernel(const float* __restrict__ lam,
                                                    const float* __restrict__ rel,
                                                    __nv_bfloat16* __restrict__ resh,
                                                    __nv_bfloat16* __restrict__ resl)
{
    const int h0 = blockIdx.x * 4;
    const int o0 = blockIdx.y * 16;
    const int bp = blockIdx.z;
    const int b = bp >> 3, head = bp & 7;

    const float* qbase = g_qkv + ((size_t)b * 3 * CC + head * HD) * NPIX;
    const float* vbase = g_qkv + ((size_t)b * 3 * CC + 2 * CC + head * HD) * NPIX;

    __shared__ float lam_s[32][17];
    __shared__ float rel_s[16][25];
    __shared__ float v_s[16][8][68];

    const int tid = threadIdx.x;
    const float scale = 0.1767766953f;

    for (int idx = tid; idx < 32 * 16; idx += 256) {
        int i = idx >> 4, oo = idx & 15;
        lam_s[i][oo] = lam[(size_t)bp * 1024 + i * 32 + o0 + oo] * scale;
    }
    for (int idx = tid; idx < 16 * 25; idx += 256)
        rel_s[idx / 25][idx % 25] = rel[(o0 + idx / 25) * 25 + idx % 25];
    for (int idx = tid; idx < 16 * 8 * 68; idx += 256) {
        int o = idx / 544;
        int rem = idx % 544;
        int rr = rem / 68, c = rem % 68;
        int h = h0 - 2 + rr, w = c - 2;
        float val = 0.f;
        if (h >= 0 && h < HH && w >= 0 && w < WW)
            val = vbase[(size_t)(o0 + o) * NPIX + h * WW + w];
        v_s[o][rr][c] = val;
    }
    __syncthreads();

    const int wr = tid >> 6;
    const int w = tid & 63;
    const int n = (h0 + wr) * WW + w;

    float qreg[32];
    #pragma unroll
    for (int i = 0; i < 32; i++) qreg[i] = qbase[(size_t)i * NPIX + n];

    const size_t obase = ((size_t)b * CC + head * HD + o0) * NPIX + n;

    #pragma unroll 2
    for (int oo = 0; oo < 16; oo++) {
        float content = 0.f;
        #pragma unroll
        for (int i = 0; i < 32; i++) content += qreg[i] * lam_s[i][oo];
        float pos = 0.f;
        #pragma unroll
        for (int dh = 0; dh < 5; dh++)
            #pragma unroll
            for (int dw = 0; dw < 5; dw++)
                pos += rel_s[oo][dh * 5 + dw] * v_s[oo][wr + dh][w + dw];
        float val = content + qreg[o0 + oo] * pos;
        __nv_bfloat16 h, l;
        bf16_split(val, h, l);
        resh[obase + (size_t)oo * NPIX] = h;
        resl[obase + (size_t)oo * NPIX] = l;
    }
}

// ---------------------------------------------------------------------------
extern "C" void kernel_launch(void* const* d_in, const int* in_sizes, int n_in,
                              void* d_out, int out_size)
{
    const float* src   = (const float*)d_in[0];
    const float* rel   = (const float*)d_in[1];
    const float* qkv_w = (const float*)d_in[2];
    const float* cpe_w = (const float*)d_in[3];
    const float* cpe_b = (const float*)d_in[4];
    const float* out_w = (const float*)d_in[5];
    const float* out_b = (const float*)d_in[6];
    float* out = (float*)d_out;

    float *pqkv, *pstats, *plam, *ppart;
    __nv_bfloat16 *psrch, *psrcl, *pxh, *pxl, *presh, *presl;
    __nv_bfloat16 *pwch, *pwcl, *pwqh, *pwql, *pwoh, *pwol;
    cudaGetSymbolAddress((void**)&pqkv,  g_qkv);
    cudaGetSymbolAddress((void**)&pstats,g_stats);
    cudaGetSymbolAddress((void**)&plam,  g_lambda);
    cudaGetSymbolAddress((void**)&ppart, g_lampart);
    cudaGetSymbolAddress((void**)&psrch, g_srch);
    cudaGetSymbolAddress((void**)&psrcl, g_srcl);
    cudaGetSymbolAddress((void**)&pxh,   g_xh);
    cudaGetSymbolAddress((void**)&pxl,   g_xl);
    cudaGetSymbolAddress((void**)&presh, g_resh);
    cudaGetSymbolAddress((void**)&presl, g_resl);
    cudaGetSymbolAddress((void**)&pwch,  g_wch);
    cudaGetSymbolAddress((void**)&pwcl,  g_wcl);
    cudaGetSymbolAddress((void**)&pwqh,  g_wqh);
    cudaGetSymbolAddress((void**)&pwql,  g_wql);
    cudaGetSymbolAddress((void**)&pwoh,  g_woh);
    cudaGetSymbolAddress((void**)&pwol,  g_wol);

    cudaFuncSetAttribute(gemm_mma, cudaFuncAttributeMaxDynamicSharedMemorySize, SMEM_BYTES);

    // 0) pre-split operands to bf16 hi/lo
    split_pass<<<16384, 256>>>(src, psrch, psrcl, BB * CC * NPIX / 4);
    wtc_kernel<<<256, 256>>>(cpe_w, pwch, pwcl);
    split_pass<<<192, 256>>>(qkv_w, pwqh, pwql, 3 * CC * CC / 4);
    split_pass<<<64, 256>>>(out_w, pwoh, pwol, CC * CC / 4);

    // 1) CPE conv (implicit GEMM K=2304) + bias + residual -> x (bf16 hi/lo)
    gemm_mma<<<dim3(32, 2, 16), 256, SMEM_BYTES>>>(pwch, pwcl, psrch, psrcl, 72, CC, 2304, 1,
                                                   nullptr, pxh, pxl, cpe_b, src);
    // 2) qkv = qkv_w @ x -> fp32
    gemm_mma<<<dim3(32, 6, 16), 256, SMEM_BYTES>>>(pwqh, pwql, pxh, pxl, 8, 3 * CC, CC, 0,
                                                   pqkv, nullptr, nullptr, nullptr, nullptr);
    // 3) softmax stats
    softmax_stats_kernel<<<4096, 256>>>(pstats);
    // 4) content lambda
    lambda_partial_kernel<<<dim3(8, 128), 256>>>(pstats, ppart);
    lambda_reduce_kernel<<<128, 256>>>(ppart, plam);
    // 5) fused content + pos-lambda -> result (bf16 hi/lo)
    fused_kernel<<<dim3(16, 2, 128), 256>>>(plam, rel, presh, presl);
    // 6) output projection -> d_out fp32
    gemm_mma<<<dim3(32, 2, 16), 256, SMEM_BYTES>>>(pwoh, pwol, presh, presl, 8, CC, CC, 0,
                                                   out, nullptr, nullptr, out_b, nullptr);
}